// round 11
// baseline (speedup 1.0000x reference)
#include <cuda_runtime.h>
#include <cuda_fp16.h>
#include <cstdint>

#define NR   399
#define DD   1024
#define RR   1024
#define LL   112
#define HALF 512

// Precomputed tables
__device__ float g_u [NR * RR];      // u[j,r] = fp[j] . W[r,:]
__device__ float g_ub[NR * RR];      // u + b
__device__ __half g_ph[LL * RR];     // P transposed [l][r], hi fp16
__device__ __half g_pl[LL * RR];     // residual lo fp16

// ---------------------------------------------------------------------------
// Direct tanh via MUFU: t = 2^(x*2*log2(e)); (t-1)/(t+1). ~1e-7 abs err.
// ---------------------------------------------------------------------------
__device__ __forceinline__ float tanh_dir(float x) {
    float t;
    asm("ex2.approx.f32 %0, %1;" : "=f"(t) : "f"(x * 2.8853900817779268f));
    float r;
    asm("rcp.approx.f32 %0, %1;" : "=f"(r) : "f"(t + 1.0f));
    return (t - 1.0f) * r;
}

__device__ __forceinline__ void mma_fp16(float* d, const uint32_t* a,
                                         uint32_t b0, uint32_t b1) {
    asm volatile(
        "mma.sync.aligned.m16n8k16.row.col.f32.f16.f16.f32 "
        "{%0,%1,%2,%3}, {%4,%5,%6,%7}, {%8,%9}, {%0,%1,%2,%3};\n"
        : "+f"(d[0]), "+f"(d[1]), "+f"(d[2]), "+f"(d[3])
        : "r"(a[0]), "r"(a[1]), "r"(a[2]), "r"(a[3]), "r"(b0), "r"(b1));
}

// ---------------------------------------------------------------------------
// Kernel A: u = fp @ W^T ; store u and u+b.  (P-split folded in as extra
// grid.x slice.)  Tile 32(j) x 64(r), BK=32, 128 threads, 4x4 microtile.
// ---------------------------------------------------------------------------
#define SAW 36
#define SBW 68

__global__ void __launch_bounds__(128, 4)
compute_u_kernel(const float* __restrict__ x,
                 const float* __restrict__ W,
                 const float* __restrict__ b,
                 const float* __restrict__ P) {
    // P-split slice: blockIdx.x == 13 -> 16 blocks x 128 threads
    if (blockIdx.x == 13) {
        int t0 = blockIdx.y * 128 + threadIdx.x;       // 0..2047
        for (int idx = t0; idx < LL * RR; idx += 2048) {
            int l = idx >> 10;
            int r = idx & 1023;
            float v = P[r * LL + l];
            __half h = __float2half_rn(v);
            g_ph[idx] = h;
            g_pl[idx] = __float2half_rn(v - __half2float(h));
        }
        return;
    }

    __shared__ float As[32][SAW];   // [k][m]
    __shared__ float Bs[32][SBW];   // [k][n]

    const int tid = threadIdx.x;
    const int j0 = blockIdx.x * 32;
    const int r0 = blockIdx.y * 64;

    const int am = tid & 31;
    const int akb = (tid >> 5) * 8;
    int jj = j0 + am; if (jj > NR - 1) jj = NR - 1;

    const int bn = tid & 63;
    const int bkh = (tid >> 6) * 16;

    const int m0 = (tid >> 4) * 4;
    const int n0 = (tid & 15) * 4;

    float ar[8], br[16];
    float acc[4][4] = {};

    {
        const float* ap = x + (size_t)jj * DD + akb;
        *(float4*)&ar[0] = *(const float4*)&ap[0];
        *(float4*)&ar[4] = *(const float4*)&ap[4];
        const float* bp = W + (size_t)(r0 + bn) * DD + bkh;
        #pragma unroll
        for (int q = 0; q < 4; q++)
            *(float4*)&br[q * 4] = *(const float4*)&bp[q * 4];
    }

    #pragma unroll 1
    for (int c = 0; c < DD / 32; c++) {
        __syncthreads();
        #pragma unroll
        for (int q = 0; q < 8; q++) As[akb + q][am] = ar[q];
        #pragma unroll
        for (int q = 0; q < 16; q++) Bs[bkh + q][bn] = br[q];
        __syncthreads();

        if (c < DD / 32 - 1) {
            const int kc = (c + 1) * 32;
            const int neg = (kc >= HALF);
            const float* ap = x + (size_t)(jj + neg) * DD + kc + akb;
            *(float4*)&ar[0] = *(const float4*)&ap[0];
            *(float4*)&ar[4] = *(const float4*)&ap[4];
            if (neg) {
                #pragma unroll
                for (int q = 0; q < 8; q++) ar[q] = -ar[q];
            }
            const float* bp = W + (size_t)(r0 + bn) * DD + kc + bkh;
            #pragma unroll
            for (int q = 0; q < 4; q++)
                *(float4*)&br[q * 4] = *(const float4*)&bp[q * 4];
        }

        #pragma unroll 8
        for (int k = 0; k < 32; k++) {
            float4 a4 = *(const float4*)&As[k][m0];
            float4 b4 = *(const float4*)&Bs[k][n0];
            acc[0][0] += a4.x * b4.x; acc[0][1] += a4.x * b4.y;
            acc[0][2] += a4.x * b4.z; acc[0][3] += a4.x * b4.w;
            acc[1][0] += a4.y * b4.x; acc[1][1] += a4.y * b4.y;
            acc[1][2] += a4.y * b4.z; acc[1][3] += a4.y * b4.w;
            acc[2][0] += a4.z * b4.x; acc[2][1] += a4.z * b4.y;
            acc[2][2] += a4.z * b4.z; acc[2][3] += a4.z * b4.w;
            acc[3][0] += a4.w * b4.x; acc[3][1] += a4.w * b4.y;
            acc[3][2] += a4.w * b4.z; acc[3][3] += a4.w * b4.w;
        }
    }

    float bv[4];
    #pragma unroll
    for (int q = 0; q < 4; q++) bv[q] = __ldg(&b[r0 + n0 + q]);

    #pragma unroll
    for (int mi = 0; mi < 4; mi++) {
        int j = j0 + m0 + mi;
        if (j < NR) {
            size_t base = (size_t)j * RR + r0 + n0;
            #pragma unroll
            for (int ni = 0; ni < 4; ni++) {
                float v = acc[mi][ni];
                g_u [base + ni] = v;
                g_ub[base + ni] = v + bv[ni];
            }
        }
    }
}

// ---------------------------------------------------------------------------
// Kernel B: HMMA pair GEMM, fp16 2-product (h single fp16, P hi/lo fp16).
// Block: 8 i x 16 j = 128 pairs (M) x 112 labels (N), K=1024 in chunks of 64.
// 8 warps = 4(M: 32 rows) x 2(N: 56 cols).
// Alignment audit: sta/stb staged via float2 (row stride 264B, %8==0);
// Bh/Bl staged via uint2 (row stride 144B, %8==0); Ah writes/reads are b32.
// ---------------------------------------------------------------------------
#define KC 64
#define SA 66   // f32 stride: 66 mod 32 = 2 -> h-gen float2 reads conflict-free
#define SH 72   // half stride: frag words g*4+tg distinct -> conflict-free
#define SB 72

__global__ void __launch_bounds__(256, 2)
pair_hmma_kernel(const float* __restrict__ ob, float* __restrict__ out) {
    __shared__ float sta[16 * SA];           // ub rows (j)
    __shared__ float stb[8 * SA];            // u rows (i)
    __shared__ __half Ah[128 * SH];          // h fp16
    __shared__ __half Bh[LL * SB];           // P hi
    __shared__ __half Bl[LL * SB];           // P lo

    const int tid = threadIdx.x;
    const int wid = tid >> 5;
    const int lane = tid & 31;
    const int g  = lane >> 2;
    const int tg = lane & 3;
    const int i0 = blockIdx.x * 8;
    const int j0 = blockIdx.y * 16;

    const int mw = wid & 3;
    const int nw = wid >> 2;
    const int mbase = mw * 32;
    const int nbase = nw * 56;

    const int hp  = tid & 127;
    const int hk0 = (tid >> 7) * 32;
    const int hjj = hp & 15;
    const int hii = hp >> 4;

    float acc[2][7][4] = {};

    #pragma unroll 1
    for (int c = 0; c < RR / KC; c++) {
        const int kc = c * KC;
        __syncthreads();

        // stage ub (16 j rows x 64) / u (8 i rows x 64)
        // global: one float4 per thread; smem: two float2 stores (8B-aligned)
        {
            int row = tid >> 4, q = tid & 15;
            int j = j0 + row; if (j > NR - 1) j = NR - 1;
            float4 va = *(const float4*)&g_ub[(size_t)j * RR + kc + q * 4];
            float2 lo = make_float2(va.x, va.y);
            float2 hi = make_float2(va.z, va.w);
            *(float2*)&sta[row * SA + q * 4]     = lo;
            *(float2*)&sta[row * SA + q * 4 + 2] = hi;
            if (tid < 128) {
                int i = i0 + row; if (i > NR - 1) i = NR - 1;
                float4 vb = *(const float4*)&g_u[(size_t)i * RR + kc + q * 4];
                *(float2*)&stb[row * SA + q * 4]     = make_float2(vb.x, vb.y);
                *(float2*)&stb[row * SA + q * 4 + 2] = make_float2(vb.z, vb.w);
            }
        }
        // stage P hi/lo: 112 rows x 64 halves; uint4 global load, 2x uint2 STS
        #pragma unroll
        for (int e = 0; e < 4; e++) {
            int idx = tid + e * 256;
            if (idx < 896) {
                int rp = idx >> 3, sg = idx & 7;
                uint4 vh = *(const uint4*)&g_ph[rp * RR + kc + sg * 8];
                uint4 vl = *(const uint4*)&g_pl[rp * RR + kc + sg * 8];
                *(uint2*)&Bh[rp * SB + sg * 8]     = make_uint2(vh.x, vh.y);
                *(uint2*)&Bh[rp * SB + sg * 8 + 4] = make_uint2(vh.z, vh.w);
                *(uint2*)&Bl[rp * SB + sg * 8]     = make_uint2(vl.x, vl.y);
                *(uint2*)&Bl[rp * SB + sg * 8 + 4] = make_uint2(vl.z, vl.w);
            }
        }
        __syncthreads();

        // h-gen: 32 k-values per thread for pair hp -> single fp16
        {
            const float* ap = &sta[hjj * SA + hk0];
            const float* bp = &stb[hii * SA + hk0];
            #pragma unroll
            for (int kk = 0; kk < 32; kk += 2) {
                float2 av = *(const float2*)&ap[kk];
                float2 bv = *(const float2*)&bp[kk];
                float h0 = tanh_dir(av.x - bv.x);
                float h1 = tanh_dir(av.y - bv.y);
                uint32_t hpk;
                asm("cvt.rn.f16x2.f32 %0, %1, %2;" : "=r"(hpk) : "f"(h1), "f"(h0));
                *(uint32_t*)&Ah[hp * SH + hk0 + kk] = hpk;
            }
        }
        __syncthreads();

        // HMMA: 4 k-steps x 2 m-frags x 7 n-frags x 2 products
        #pragma unroll
        for (int ks = 0; ks < KC; ks += 16) {
            uint32_t ah[2][4];
            #pragma unroll
            for (int mf = 0; mf < 2; mf++) {
                int m0 = mbase + mf * 16;
                ah[mf][0] = *(const uint32_t*)&Ah[(m0 + g)     * SH + ks + tg * 2];
                ah[mf][1] = *(const uint32_t*)&Ah[(m0 + g + 8) * SH + ks + tg * 2];
                ah[mf][2] = *(const uint32_t*)&Ah[(m0 + g)     * SH + ks + tg * 2 + 8];
                ah[mf][3] = *(const uint32_t*)&Ah[(m0 + g + 8) * SH + ks + tg * 2 + 8];
            }
            #pragma unroll
            for (int nf = 0; nf < 7; nf++) {
                int n = nbase + nf * 8 + g;
                uint32_t bh0 = *(const uint32_t*)&Bh[n * SB + ks + tg * 2];
                uint32_t bh1 = *(const uint32_t*)&Bh[n * SB + ks + tg * 2 + 8];
                uint32_t bl0 = *(const uint32_t*)&Bl[n * SB + ks + tg * 2];
                uint32_t bl1 = *(const uint32_t*)&Bl[n * SB + ks + tg * 2 + 8];
                #pragma unroll
                for (int mf = 0; mf < 2; mf++) {
                    mma_fp16(acc[mf][nf], ah[mf], bh0, bh1);
                    mma_fp16(acc[mf][nf], ah[mf], bl0, bl1);
                }
            }
        }
    }

    // epilogue
    #pragma unroll
    for (int mf = 0; mf < 2; mf++) {
        const int ii = (mbase >> 4) + mf;
        const int i = i0 + ii;
        const bool iok = (i < NR);
        const int jA = j0 + g;
        const int jB = j0 + g + 8;
        const bool jAok = iok && (jA < NR);
        const bool jBok = iok && (jB < NR);
        float* rowA = out + ((size_t)i * NR + jA) * LL;
        float* rowB = out + ((size_t)i * NR + jB) * LL;
        #pragma unroll
        for (int nf = 0; nf < 7; nf++) {
            int l = nbase + nf * 8 + tg * 2;
            float b0 = __ldg(&ob[l]);
            float b1 = __ldg(&ob[l + 1]);
            if (jAok) {
                float2 v = { acc[mf][nf][0] + b0, acc[mf][nf][1] + b1 };
                *(float2*)&rowA[l] = v;
            }
            if (jBok) {
                float2 v = { acc[mf][nf][2] + b0, acc[mf][nf][3] + b1 };
                *(float2*)&rowB[l] = v;
            }
        }
    }
}

// ---------------------------------------------------------------------------
// Launch. Inputs: x(400x1024), W(1024x1024), b(1024), P(1024x112), out_bias(112)
// ---------------------------------------------------------------------------
extern "C" void kernel_launch(void* const* d_in, const int* in_sizes, int n_in,
                              void* d_out, int out_size) {
    const float* x  = (const float*)d_in[0];
    const float* W  = (const float*)d_in[1];
    const float* b  = (const float*)d_in[2];
    const float* P  = (const float*)d_in[3];
    const float* ob = (const float*)d_in[4];
    float* out = (float*)d_out;

    compute_u_kernel<<<dim3(14, 16), 128>>>(x, W, b, P);   // x-slice 13 = P-split
    pair_hmma_kernel<<<dim3(50, 25), 256>>>(ob, out);
}

// round 13
// speedup vs baseline: 1.3836x; 1.3836x over previous
#include <cuda_runtime.h>
#include <cuda_fp16.h>
#include <cstdint>

#define NR   399
#define DD   1024
#define RR   1024
#define LL   112
#define HALF 512

// Precomputed tables
__device__ float g_u [NR * RR];      // u[j,r] = fp[j] . W[r,:]
__device__ float g_ub[NR * RR];      // u + b
__device__ __half g_ph[LL * RR];     // P transposed [l][r], hi fp16
__device__ __half g_pl[LL * RR];     // residual lo fp16

// ---------------------------------------------------------------------------
// Direct tanh via MUFU: t = 2^(x*2*log2(e)); (t-1)/(t+1). ~1e-7 abs err.
// ---------------------------------------------------------------------------
__device__ __forceinline__ float tanh_dir(float x) {
    float t;
    asm("ex2.approx.f32 %0, %1;" : "=f"(t) : "f"(x * 2.8853900817779268f));
    float r;
    asm("rcp.approx.f32 %0, %1;" : "=f"(r) : "f"(t + 1.0f));
    return (t - 1.0f) * r;
}

__device__ __forceinline__ uint32_t smem_u32(const void* p) {
    uint32_t a;
    asm("{ .reg .u64 t; cvta.to.shared.u64 t, %1; cvt.u32.u64 %0, t; }" : "=r"(a) : "l"(p));
    return a;
}

__device__ __forceinline__ void ldsm_x4(uint32_t& r0, uint32_t& r1,
                                        uint32_t& r2, uint32_t& r3, uint32_t addr) {
    asm volatile("ldmatrix.sync.aligned.m8n8.x4.shared.b16 {%0,%1,%2,%3}, [%4];"
        : "=r"(r0), "=r"(r1), "=r"(r2), "=r"(r3) : "r"(addr));
}

__device__ __forceinline__ void mma_fp16(float* d, const uint32_t* a,
                                         uint32_t b0, uint32_t b1) {
    asm volatile(
        "mma.sync.aligned.m16n8k16.row.col.f32.f16.f16.f32 "
        "{%0,%1,%2,%3}, {%4,%5,%6,%7}, {%8,%9}, {%0,%1,%2,%3};\n"
        : "+f"(d[0]), "+f"(d[1]), "+f"(d[2]), "+f"(d[3])
        : "r"(a[0]), "r"(a[1]), "r"(a[2]), "r"(a[3]), "r"(b0), "r"(b1));
}

// ---------------------------------------------------------------------------
// Kernel A: u = fp @ W^T ; store u and u+b.  (P-split folded in as extra
// grid.x slice.)  Tile 32(j) x 64(r), BK=32, 128 threads, 4x4 microtile.
// ---------------------------------------------------------------------------
#define SAW 36
#define SBW 68

__global__ void __launch_bounds__(128, 4)
compute_u_kernel(const float* __restrict__ x,
                 const float* __restrict__ W,
                 const float* __restrict__ b,
                 const float* __restrict__ P) {
    if (blockIdx.x == 13) {
        int t0 = blockIdx.y * 128 + threadIdx.x;
        for (int idx = t0; idx < LL * RR; idx += 2048) {
            int l = idx >> 10;
            int r = idx & 1023;
            float v = P[r * LL + l];
            __half h = __float2half_rn(v);
            g_ph[idx] = h;
            g_pl[idx] = __float2half_rn(v - __half2float(h));
        }
        return;
    }

    __shared__ float As[32][SAW];
    __shared__ float Bs[32][SBW];

    const int tid = threadIdx.x;
    const int j0 = blockIdx.x * 32;
    const int r0 = blockIdx.y * 64;

    const int am = tid & 31;
    const int akb = (tid >> 5) * 8;
    int jj = j0 + am; if (jj > NR - 1) jj = NR - 1;

    const int bn = tid & 63;
    const int bkh = (tid >> 6) * 16;

    const int m0 = (tid >> 4) * 4;
    const int n0 = (tid & 15) * 4;

    float ar[8], br[16];
    float acc[4][4] = {};

    {
        const float* ap = x + (size_t)jj * DD + akb;
        *(float4*)&ar[0] = *(const float4*)&ap[0];
        *(float4*)&ar[4] = *(const float4*)&ap[4];
        const float* bp = W + (size_t)(r0 + bn) * DD + bkh;
        #pragma unroll
        for (int q = 0; q < 4; q++)
            *(float4*)&br[q * 4] = *(const float4*)&bp[q * 4];
    }

    #pragma unroll 1
    for (int c = 0; c < DD / 32; c++) {
        __syncthreads();
        #pragma unroll
        for (int q = 0; q < 8; q++) As[akb + q][am] = ar[q];
        #pragma unroll
        for (int q = 0; q < 16; q++) Bs[bkh + q][bn] = br[q];
        __syncthreads();

        if (c < DD / 32 - 1) {
            const int kc = (c + 1) * 32;
            const int neg = (kc >= HALF);
            const float* ap = x + (size_t)(jj + neg) * DD + kc + akb;
            *(float4*)&ar[0] = *(const float4*)&ap[0];
            *(float4*)&ar[4] = *(const float4*)&ap[4];
            if (neg) {
                #pragma unroll
                for (int q = 0; q < 8; q++) ar[q] = -ar[q];
            }
            const float* bp = W + (size_t)(r0 + bn) * DD + kc + bkh;
            #pragma unroll
            for (int q = 0; q < 4; q++)
                *(float4*)&br[q * 4] = *(const float4*)&bp[q * 4];
        }

        #pragma unroll 8
        for (int k = 0; k < 32; k++) {
            float4 a4 = *(const float4*)&As[k][m0];
            float4 b4 = *(const float4*)&Bs[k][n0];
            acc[0][0] += a4.x * b4.x; acc[0][1] += a4.x * b4.y;
            acc[0][2] += a4.x * b4.z; acc[0][3] += a4.x * b4.w;
            acc[1][0] += a4.y * b4.x; acc[1][1] += a4.y * b4.y;
            acc[1][2] += a4.y * b4.z; acc[1][3] += a4.y * b4.w;
            acc[2][0] += a4.z * b4.x; acc[2][1] += a4.z * b4.y;
            acc[2][2] += a4.z * b4.z; acc[2][3] += a4.z * b4.w;
            acc[3][0] += a4.w * b4.x; acc[3][1] += a4.w * b4.y;
            acc[3][2] += a4.w * b4.z; acc[3][3] += a4.w * b4.w;
        }
    }

    float bv[4];
    #pragma unroll
    for (int q = 0; q < 4; q++) bv[q] = __ldg(&b[r0 + n0 + q]);

    #pragma unroll
    for (int mi = 0; mi < 4; mi++) {
        int j = j0 + m0 + mi;
        if (j < NR) {
            size_t base = (size_t)j * RR + r0 + n0;
            #pragma unroll
            for (int ni = 0; ni < 4; ni++) {
                float v = acc[mi][ni];
                g_u [base + ni] = v;
                g_ub[base + ni] = v + bv[ni];
            }
        }
    }
}

// ---------------------------------------------------------------------------
// Kernel B: HMMA pair GEMM, fp16 2-product, ldmatrix fragment loads.
// Block: 8 i x 16 j = 128 pairs (M) x 112 labels (N), K=1024 in chunks of 32.
// 8 warps = 4(M: 32 rows) x 2(N: 56 cols). KC=32 (R8 structure).
// Strides: SH=SB=40 halves = 80B rows -> 16B-aligned, 5 units coprime 8:
// conflict-free ldmatrix.
// ---------------------------------------------------------------------------
#define KC 32
#define SA 34   // f32 stride for u/ub staging (R8-proven)
#define SH 40   // half stride, A (h) tile
#define SB 40   // half stride, B (P) tiles

__global__ void __launch_bounds__(256, 2)
pair_hmma_kernel(const float* __restrict__ ob, float* __restrict__ out) {
    __shared__ float sta[16 * SA];           // ub rows (j)
    __shared__ float stb[8 * SA];            // u rows (i)
    __shared__ __half Ah[128 * SH];          // h fp16
    __shared__ __half Bh[LL * SB];           // P hi
    __shared__ __half Bl[LL * SB];           // P lo

    const int tid = threadIdx.x;
    const int wid = tid >> 5;
    const int lane = tid & 31;
    const int g  = lane >> 2;
    const int tg = lane & 3;
    const int i0 = blockIdx.x * 8;
    const int j0 = blockIdx.y * 16;

    const int mw = wid & 3;
    const int nw = wid >> 2;
    const int mbase = mw * 32;
    const int nbase = nw * 56;

    const int hp  = tid & 127;
    const int hk0 = (tid >> 7) * 16;
    const int hjj = hp & 15;
    const int hii = hp >> 4;

    // ldmatrix per-lane addresses (halves -> bytes)
    const int lr = lane & 7;          // row within 8x8 matrix
    const int lmi = lane >> 3;        // matrix index 0..3
    const uint32_t ah_base = smem_u32(Ah);
    const uint32_t bh_base = smem_u32(Bh);
    const uint32_t bl_base = smem_u32(Bl);
    // A frag (per mf, per ks): row = mbase + mf*16 + lr + (lmi&1)*8, col = ks + (lmi>>1)*8
    const uint32_t a_row_off = (uint32_t)(mbase + lr + (lmi & 1) * 8) * SH * 2;
    const uint32_t a_col_off = (uint32_t)((lmi >> 1) * 8) * 2;
    // B frag (per nf): row = nbase + nf*8 + lr, col = (lmi&1)*8 + (lmi>>1)*16
    const uint32_t b_row_off = (uint32_t)(nbase + lr) * SB * 2;
    const uint32_t b_col_off = (uint32_t)((lmi & 1) * 8 + (lmi >> 1) * 16) * 2;

    float acc[2][7][4] = {};

    #pragma unroll 1
    for (int c = 0; c < RR / KC; c++) {
        const int kc = c * KC;
        __syncthreads();

        // stage ub (16 j rows x 32) / u (8 i rows x 32): float2 per thread
        {
            int row = tid >> 4, q = tid & 15;
            int j = j0 + row; if (j > NR - 1) j = NR - 1;
            *(float2*)&sta[row * SA + q * 2] =
                *(const float2*)&g_ub[(size_t)j * RR + kc + q * 2];
            if (tid < 128) {
                int i = i0 + row; if (i > NR - 1) i = NR - 1;
                *(float2*)&stb[row * SA + q * 2] =
                    *(const float2*)&g_u[(size_t)i * RR + kc + q * 2];
            }
        }
        // stage P hi/lo: 112 rows x 32 halves; uint4 LDG, 2x uint2 STS (8B ok)
        #pragma unroll
        for (int e = 0; e < 2; e++) {
            int idx = tid + e * 256;
            if (idx < 448) {
                int rp = idx >> 2, sg = idx & 3;
                uint4 vh = *(const uint4*)&g_ph[rp * RR + kc + sg * 8];
                uint4 vl = *(const uint4*)&g_pl[rp * RR + kc + sg * 8];
                *(uint2*)&Bh[rp * SB + sg * 8]     = make_uint2(vh.x, vh.y);
                *(uint2*)&Bh[rp * SB + sg * 8 + 4] = make_uint2(vh.z, vh.w);
                *(uint2*)&Bl[rp * SB + sg * 8]     = make_uint2(vl.x, vl.y);
                *(uint2*)&Bl[rp * SB + sg * 8 + 4] = make_uint2(vl.z, vl.w);
            }
        }
        __syncthreads();

        // h-gen: 16 k-values per thread for pair hp -> fp16
        {
            const float* ap = &sta[hjj * SA + hk0];
            const float* bp = &stb[hii * SA + hk0];
            #pragma unroll
            for (int kk = 0; kk < 16; kk += 2) {
                float2 av = *(const float2*)&ap[kk];
                float2 bv = *(const float2*)&bp[kk];
                float h0 = tanh_dir(av.x - bv.x);
                float h1 = tanh_dir(av.y - bv.y);
                uint32_t hpk;
                asm("cvt.rn.f16x2.f32 %0, %1, %2;" : "=r"(hpk) : "f"(h1), "f"(h0));
                *(uint32_t*)&Ah[hp * SH + hk0 + kk] = hpk;
            }
        }
        __syncthreads();

        // A frags: 2 mf x 2 ks, one ldmatrix.x4 each
        uint32_t a[2][2][4];   // [ks][mf][reg]
        #pragma unroll
        for (int ks = 0; ks < 2; ks++) {
            #pragma unroll
            for (int mf = 0; mf < 2; mf++) {
                uint32_t addr = ah_base + a_row_off + (uint32_t)(mf * 16) * SH * 2
                              + a_col_off + (uint32_t)(ks * 16) * 2;
                ldsm_x4(a[ks][mf][0], a[ks][mf][1], a[ks][mf][2], a[ks][mf][3], addr);
            }
        }

        // B frags + MMA: per nf, one x4 from Bh (both ks) + one from Bl
        #pragma unroll
        for (int nf = 0; nf < 7; nf++) {
            uint32_t boff = b_row_off + (uint32_t)(nf * 8) * SB * 2 + b_col_off;
            uint32_t bhr[4], blr[4];
            ldsm_x4(bhr[0], bhr[1], bhr[2], bhr[3], bh_base + boff);
            ldsm_x4(blr[0], blr[1], blr[2], blr[3], bl_base + boff);
            #pragma unroll
            for (int ks = 0; ks < 2; ks++) {
                #pragma unroll
                for (int mf = 0; mf < 2; mf++) {
                    mma_fp16(acc[mf][nf], a[ks][mf], bhr[ks * 2], bhr[ks * 2 + 1]);
                    mma_fp16(acc[mf][nf], a[ks][mf], blr[ks * 2], blr[ks * 2 + 1]);
                }
            }
        }
    }

    // epilogue
    #pragma unroll
    for (int mf = 0; mf < 2; mf++) {
        const int ii = (mbase >> 4) + mf;
        const int i = i0 + ii;
        const bool iok = (i < NR);
        const int jA = j0 + g;
        const int jB = j0 + g + 8;
        const bool jAok = iok && (jA < NR);
        const bool jBok = iok && (jB < NR);
        float* rowA = out + ((size_t)i * NR + jA) * LL;
        float* rowB = out + ((size_t)i * NR + jB) * LL;
        #pragma unroll
        for (int nf = 0; nf < 7; nf++) {
            int l = nbase + nf * 8 + tg * 2;
            float b0 = __ldg(&ob[l]);
            float b1 = __ldg(&ob[l + 1]);
            if (jAok) {
                float2 v = { acc[mf][nf][0] + b0, acc[mf][nf][1] + b1 };
                *(float2*)&rowA[l] = v;
            }
            if (jBok) {
                float2 v = { acc[mf][nf][2] + b0, acc[mf][nf][3] + b1 };
                *(float2*)&rowB[l] = v;
            }
        }
    }
}

// ---------------------------------------------------------------------------
// Launch. Inputs: x(400x1024), W(1024x1024), b(1024), P(1024x112), out_bias(112)
// ---------------------------------------------------------------------------
extern "C" void kernel_launch(void* const* d_in, const int* in_sizes, int n_in,
                              void* d_out, int out_size) {
    const float* x  = (const float*)d_in[0];
    const float* W  = (const float*)d_in[1];
    const float* b  = (const float*)d_in[2];
    const float* P  = (const float*)d_in[3];
    const float* ob = (const float*)d_in[4];
    float* out = (float*)d_out;

    compute_u_kernel<<<dim3(14, 16), 128>>>(x, W, b, P);   // x-slice 13 = P-split
    pair_hmma_kernel<<<dim3(50, 25), 256>>>(ob, out);
}

// round 15
// speedup vs baseline: 1.7090x; 1.2352x over previous
#include <cuda_runtime.h>
#include <cuda_fp16.h>
#include <cstdint>

#define NR   399
#define DD   1024
#define RR   1024
#define LL   112
#define HALF 512

// Precomputed tables
__device__ float g_u [NR * RR];      // u[j,r] = fp[j] . W[r,:]
__device__ float g_ub[NR * RR];      // u + b
__device__ __half g_ph[LL * RR];     // P transposed [l][r], hi fp16
__device__ __half g_pl[LL * RR];     // residual lo fp16

// ---------------------------------------------------------------------------
// Direct tanh via MUFU: t = 2^(x*2*log2(e)); (t-1)/(t+1). ~1e-7 abs err.
// ---------------------------------------------------------------------------
__device__ __forceinline__ float tanh_dir(float x) {
    float t;
    asm("ex2.approx.f32 %0, %1;" : "=f"(t) : "f"(x * 2.8853900817779268f));
    float r;
    asm("rcp.approx.f32 %0, %1;" : "=f"(r) : "f"(t + 1.0f));
    return (t - 1.0f) * r;
}

__device__ __forceinline__ uint32_t smem_u32(const void* p) {
    uint32_t a;
    asm("{ .reg .u64 t; cvta.to.shared.u64 t, %1; cvt.u32.u64 %0, t; }" : "=r"(a) : "l"(p));
    return a;
}

__device__ __forceinline__ void ldsm_x4(uint32_t& r0, uint32_t& r1,
                                        uint32_t& r2, uint32_t& r3, uint32_t addr) {
    asm volatile("ldmatrix.sync.aligned.m8n8.x4.shared.b16 {%0,%1,%2,%3}, [%4];"
        : "=r"(r0), "=r"(r1), "=r"(r2), "=r"(r3) : "r"(addr));
}

__device__ __forceinline__ void mma_fp16(float* d, const uint32_t* a,
                                         uint32_t b0, uint32_t b1) {
    asm volatile(
        "mma.sync.aligned.m16n8k16.row.col.f32.f16.f16.f32 "
        "{%0,%1,%2,%3}, {%4,%5,%6,%7}, {%8,%9}, {%0,%1,%2,%3};\n"
        : "+f"(d[0]), "+f"(d[1]), "+f"(d[2]), "+f"(d[3])
        : "r"(a[0]), "r"(a[1]), "r"(a[2]), "r"(a[3]), "r"(b0), "r"(b1));
}

#define CP_A8(dst, src) \
    asm volatile("cp.async.ca.shared.global [%0], [%1], 8;" :: "r"(dst), "l"(src))
#define CP_A16(dst, src) \
    asm volatile("cp.async.cg.shared.global [%0], [%1], 16;" :: "r"(dst), "l"(src))
#define CP_COMMIT() asm volatile("cp.async.commit_group;" ::: "memory")
#define CP_WAIT1()  asm volatile("cp.async.wait_group 1;" ::: "memory")
#define CP_WAIT0()  asm volatile("cp.async.wait_group 0;" ::: "memory")

// ---------------------------------------------------------------------------
// Kernel A: u = fp @ W^T ; store u and u+b. (P-split folded in as grid.x==13.)
// ---------------------------------------------------------------------------
#define SAW 36
#define SBW 68

__global__ void __launch_bounds__(128, 4)
compute_u_kernel(const float* __restrict__ x,
                 const float* __restrict__ W,
                 const float* __restrict__ b,
                 const float* __restrict__ P) {
    if (blockIdx.x == 13) {
        int t0 = blockIdx.y * 128 + threadIdx.x;
        for (int idx = t0; idx < LL * RR; idx += 2048) {
            int l = idx >> 10;
            int r = idx & 1023;
            float v = P[r * LL + l];
            __half h = __float2half_rn(v);
            g_ph[idx] = h;
            g_pl[idx] = __float2half_rn(v - __half2float(h));
        }
        return;
    }

    __shared__ float As[32][SAW];
    __shared__ float Bs[32][SBW];

    const int tid = threadIdx.x;
    const int j0 = blockIdx.x * 32;
    const int r0 = blockIdx.y * 64;

    const int am = tid & 31;
    const int akb = (tid >> 5) * 8;
    int jj = j0 + am; if (jj > NR - 1) jj = NR - 1;

    const int bn = tid & 63;
    const int bkh = (tid >> 6) * 16;

    const int m0 = (tid >> 4) * 4;
    const int n0 = (tid & 15) * 4;

    float ar[8], br[16];
    float acc[4][4] = {};

    {
        const float* ap = x + (size_t)jj * DD + akb;
        *(float4*)&ar[0] = *(const float4*)&ap[0];
        *(float4*)&ar[4] = *(const float4*)&ap[4];
        const float* bp = W + (size_t)(r0 + bn) * DD + bkh;
        #pragma unroll
        for (int q = 0; q < 4; q++)
            *(float4*)&br[q * 4] = *(const float4*)&bp[q * 4];
    }

    #pragma unroll 1
    for (int c = 0; c < DD / 32; c++) {
        __syncthreads();
        #pragma unroll
        for (int q = 0; q < 8; q++) As[akb + q][am] = ar[q];
        #pragma unroll
        for (int q = 0; q < 16; q++) Bs[bkh + q][bn] = br[q];
        __syncthreads();

        if (c < DD / 32 - 1) {
            const int kc = (c + 1) * 32;
            const int neg = (kc >= HALF);
            const float* ap = x + (size_t)(jj + neg) * DD + kc + akb;
            *(float4*)&ar[0] = *(const float4*)&ap[0];
            *(float4*)&ar[4] = *(const float4*)&ap[4];
            if (neg) {
                #pragma unroll
                for (int q = 0; q < 8; q++) ar[q] = -ar[q];
            }
            const float* bp = W + (size_t)(r0 + bn) * DD + kc + bkh;
            #pragma unroll
            for (int q = 0; q < 4; q++)
                *(float4*)&br[q * 4] = *(const float4*)&bp[q * 4];
        }

        #pragma unroll 8
        for (int k = 0; k < 32; k++) {
            float4 a4 = *(const float4*)&As[k][m0];
            float4 b4 = *(const float4*)&Bs[k][n0];
            acc[0][0] += a4.x * b4.x; acc[0][1] += a4.x * b4.y;
            acc[0][2] += a4.x * b4.z; acc[0][3] += a4.x * b4.w;
            acc[1][0] += a4.y * b4.x; acc[1][1] += a4.y * b4.y;
            acc[1][2] += a4.y * b4.z; acc[1][3] += a4.y * b4.w;
            acc[2][0] += a4.z * b4.x; acc[2][1] += a4.z * b4.y;
            acc[2][2] += a4.z * b4.z; acc[2][3] += a4.z * b4.w;
            acc[3][0] += a4.w * b4.x; acc[3][1] += a4.w * b4.y;
            acc[3][2] += a4.w * b4.z; acc[3][3] += a4.w * b4.w;
        }
    }

    float bv[4];
    #pragma unroll
    for (int q = 0; q < 4; q++) bv[q] = __ldg(&b[r0 + n0 + q]);

    #pragma unroll
    for (int mi = 0; mi < 4; mi++) {
        int j = j0 + m0 + mi;
        if (j < NR) {
            size_t base = (size_t)j * RR + r0 + n0;
            #pragma unroll
            for (int ni = 0; ni < 4; ni++) {
                float v = acc[mi][ni];
                g_u [base + ni] = v;
                g_ub[base + ni] = v + bv[ni];
            }
        }
    }
}

// ---------------------------------------------------------------------------
// Kernel B: HMMA pair GEMM, fp16 2-product, ldmatrix frags, cp.async pipeline.
// Block: 8 i x 16 j = 128 pairs (M) x 112 labels (N), K chunks of 32, double-
// buffered smem staged by cp.async one chunk ahead.
// P staging: R13-proven map — 448 segments (112 rows x 4 x 8 halves), 16B each.
// ---------------------------------------------------------------------------
#define KC 32
#define SA 34   // f32 stride (136B rows -> 8B-aligned cp.async)
#define SH 40   // half stride (80B rows, 16B-aligned, conflict-free ldmatrix)
#define SB 40

#define STA_SZ (16 * SA * 4)            // 2176 B per buffer
#define STB_SZ (8 * SA * 4)             // 1088
#define BH_SZ  (LL * SB * 2)            // 8960
#define AH_SZ  (128 * SH * 2)           // 10240

#define OFF_STA 0
#define OFF_STB (OFF_STA + 2 * STA_SZ)          // 4352
#define OFF_BH  (OFF_STB + 2 * STB_SZ)          // 6528
#define OFF_BL  (OFF_BH + 2 * BH_SZ)            // 24448
#define OFF_AH  (OFF_BL + 2 * BH_SZ)            // 42368
#define SMEM_TOTAL (OFF_AH + 2 * AH_SZ)         // 62848

#define NCHUNK (RR / KC)

__global__ void __launch_bounds__(256, 2)
pair_hmma_kernel(const float* __restrict__ ob, float* __restrict__ out) {
    extern __shared__ char smem[];
    const uint32_t sbase = smem_u32(smem);

    const int tid = threadIdx.x;
    const int wid = tid >> 5;
    const int lane = tid & 31;
    const int g  = lane >> 2;
    const int tg = lane & 3;
    const int i0 = blockIdx.x * 8;
    const int j0 = blockIdx.y * 16;

    const int mw = wid & 3;
    const int nw = wid >> 2;
    const int mbase = mw * 32;
    const int nbase = nw * 56;

    const int hp  = tid & 127;
    const int hk0 = (tid >> 7) * 16;
    const int hjj = hp & 15;
    const int hii = hp >> 4;

    // staging maps: u/ub rows (8B per thread)
    const int srow = tid >> 4, sq = tid & 15;
    int sj = j0 + srow; if (sj > NR - 1) sj = NR - 1;
    int si = i0 + srow; if (si > NR - 1) si = NR - 1;
    const uint64_t gub_addr = (uint64_t)__cvta_generic_to_global(
        (void*)(g_ub + (size_t)sj * RR + sq * 2));
    const uint64_t gu_addr = (uint64_t)__cvta_generic_to_global(
        (void*)(g_u + (size_t)si * RR + sq * 2));

    // P staging map (R13-proven coverage): e in {0,1}, idx = tid + e*256 < 448
    // rp = idx>>2 (row 0..111), sg = idx&3 (16B segment), covers all 32 halves.
    const int pidx0 = tid;
    const int pidx1 = tid + 256;
    const int prp0 = pidx0 >> 2, psg0 = pidx0 & 3;
    const int prp1 = pidx1 >> 2, psg1 = pidx1 & 3;
    const bool pok1 = (pidx1 < 448);               // pidx0 < 448 always (tid<256)
    const uint64_t gph0 = (uint64_t)__cvta_generic_to_global(
        (void*)(g_ph + (size_t)prp0 * RR + psg0 * 8));
    const uint64_t gpl0 = (uint64_t)__cvta_generic_to_global(
        (void*)(g_pl + (size_t)prp0 * RR + psg0 * 8));
    const uint64_t gph1 = (uint64_t)__cvta_generic_to_global(
        (void*)(g_ph + (size_t)prp1 * RR + psg1 * 8));
    const uint64_t gpl1 = (uint64_t)__cvta_generic_to_global(
        (void*)(g_pl + (size_t)prp1 * RR + psg1 * 8));

    // ldmatrix per-lane addressing
    const int lr = lane & 7;
    const int lmi = lane >> 3;
    const uint32_t a_row_off = (uint32_t)(mbase + lr + (lmi & 1) * 8) * SH * 2;
    const uint32_t a_col_off = (uint32_t)((lmi >> 1) * 8) * 2;
    const uint32_t b_row_off = (uint32_t)(nbase + lr) * SB * 2;
    const uint32_t b_col_off = (uint32_t)((lmi & 1) * 8 + (lmi >> 1) * 16) * 2;

    float acc[2][7][4] = {};

    // ---- stage chunk kc into buffer s via cp.async ----
    auto stage = [&](int kc, int s) {
        uint32_t dsta = sbase + OFF_STA + s * STA_SZ + (srow * SA + sq * 2) * 4;
        CP_A8(dsta, gub_addr + (size_t)kc * 4);
        if (tid < 128) {
            uint32_t dstb = sbase + OFF_STB + s * STB_SZ + (srow * SA + sq * 2) * 4;
            CP_A8(dstb, gu_addr + (size_t)kc * 4);
        }
        // P hi/lo: full coverage, 16B per segment
        {
            uint32_t dbh = sbase + OFF_BH + s * BH_SZ + (prp0 * SB + psg0 * 8) * 2;
            uint32_t dbl = sbase + OFF_BL + s * BH_SZ + (prp0 * SB + psg0 * 8) * 2;
            CP_A16(dbh, gph0 + (size_t)kc * 2);
            CP_A16(dbl, gpl0 + (size_t)kc * 2);
        }
        if (pok1) {
            uint32_t dbh = sbase + OFF_BH + s * BH_SZ + (prp1 * SB + psg1 * 8) * 2;
            uint32_t dbl = sbase + OFF_BL + s * BH_SZ + (prp1 * SB + psg1 * 8) * 2;
            CP_A16(dbh, gph1 + (size_t)kc * 2);
            CP_A16(dbl, gpl1 + (size_t)kc * 2);
        }
    };

    stage(0, 0);
    CP_COMMIT();

    #pragma unroll 1
    for (int c = 0; c < NCHUNK; c++) {
        const int s = c & 1;

        __syncthreads();   // all warps done with buffers from iteration c-1
        if (c + 1 < NCHUNK) {
            stage((c + 1) * KC, 1 - s);
            CP_COMMIT();
            CP_WAIT1();    // chunk c resident, chunk c+1 in flight
        } else {
            CP_WAIT0();
        }
        __syncthreads();

        // h-gen: 16 k-values per thread for pair hp -> fp16 into Ah[s]
        {
            const float* ap = (const float*)(smem + OFF_STA + s * STA_SZ)
                            + hjj * SA + hk0;
            const float* bp = (const float*)(smem + OFF_STB + s * STB_SZ)
                            + hii * SA + hk0;
            __half* ah = (__half*)(smem + OFF_AH + s * AH_SZ);
            #pragma unroll
            for (int kk = 0; kk < 16; kk += 2) {
                float2 av = *(const float2*)&ap[kk];
                float2 bv = *(const float2*)&bp[kk];
                float h0 = tanh_dir(av.x - bv.x);
                float h1 = tanh_dir(av.y - bv.y);
                uint32_t hpk;
                asm("cvt.rn.f16x2.f32 %0, %1, %2;" : "=r"(hpk) : "f"(h1), "f"(h0));
                *(uint32_t*)&ah[hp * SH + hk0 + kk] = hpk;
            }
        }
        __syncthreads();

        const uint32_t ah_base = sbase + OFF_AH + s * AH_SZ;
        const uint32_t bh_base = sbase + OFF_BH + s * BH_SZ;
        const uint32_t bl_base = sbase + OFF_BL + s * BH_SZ;

        // A frags: 2 mf x 2 ks
        uint32_t a[2][2][4];
        #pragma unroll
        for (int ks = 0; ks < 2; ks++) {
            #pragma unroll
            for (int mf = 0; mf < 2; mf++) {
                uint32_t addr = ah_base + a_row_off + (uint32_t)(mf * 16) * SH * 2
                              + a_col_off + (uint32_t)(ks * 16) * 2;
                ldsm_x4(a[ks][mf][0], a[ks][mf][1], a[ks][mf][2], a[ks][mf][3], addr);
            }
        }

        // B frags + MMA
        #pragma unroll
        for (int nf = 0; nf < 7; nf++) {
            uint32_t boff = b_row_off + (uint32_t)(nf * 8) * SB * 2 + b_col_off;
            uint32_t bhr[4], blr[4];
            ldsm_x4(bhr[0], bhr[1], bhr[2], bhr[3], bh_base + boff);
            ldsm_x4(blr[0], blr[1], blr[2], blr[3], bl_base + boff);
            #pragma unroll
            for (int ks = 0; ks < 2; ks++) {
                #pragma unroll
                for (int mf = 0; mf < 2; mf++) {
                    mma_fp16(acc[mf][nf], a[ks][mf], bhr[ks * 2], bhr[ks * 2 + 1]);
                    mma_fp16(acc[mf][nf], a[ks][mf], blr[ks * 2], blr[ks * 2 + 1]);
                }
            }
        }
    }

    // epilogue
    #pragma unroll
    for (int mf = 0; mf < 2; mf++) {
        const int ii = (mbase >> 4) + mf;
        const int i = i0 + ii;
        const bool iok = (i < NR);
        const int jA = j0 + g;
        const int jB = j0 + g + 8;
        const bool jAok = iok && (jA < NR);
        const bool jBok = iok && (jB < NR);
        float* rowA = out + ((size_t)i * NR + jA) * LL;
        float* rowB = out + ((size_t)i * NR + jB) * LL;
        #pragma unroll
        for (int nf = 0; nf < 7; nf++) {
            int l = nbase + nf * 8 + tg * 2;
            float b0 = __ldg(&ob[l]);
            float b1 = __ldg(&ob[l + 1]);
            if (jAok) {
                float2 v = { acc[mf][nf][0] + b0, acc[mf][nf][1] + b1 };
                *(float2*)&rowA[l] = v;
            }
            if (jBok) {
                float2 v = { acc[mf][nf][2] + b0, acc[mf][nf][3] + b1 };
                *(float2*)&rowB[l] = v;
            }
        }
    }
}

// ---------------------------------------------------------------------------
// Launch. Inputs: x(400x1024), W(1024x1024), b(1024), P(1024x112), out_bias(112)
// ---------------------------------------------------------------------------
extern "C" void kernel_launch(void* const* d_in, const int* in_sizes, int n_in,
                              void* d_out, int out_size) {
    const float* x  = (const float*)d_in[0];
    const float* W  = (const float*)d_in[1];
    const float* b  = (const float*)d_in[2];
    const float* P  = (const float*)d_in[3];
    const float* ob = (const float*)d_in[4];
    float* out = (float*)d_out;

    cudaFuncSetAttribute(pair_hmma_kernel,
                         cudaFuncAttributeMaxDynamicSharedMemorySize, SMEM_TOTAL);

    compute_u_kernel<<<dim3(14, 16), 128>>>(x, W, b, P);
    pair_hmma_kernel<<<dim3(50, 25), 256, SMEM_TOTAL>>>(ob, out);
}

// round 16
// speedup vs baseline: 2.2337x; 1.3070x over previous
#include <cuda_runtime.h>
#include <cuda_fp16.h>
#include <cstdint>

#define NR   399
#define DD   1024
#define RR   1024
#define LL   112
#define HALF 512

// Precomputed tables
__device__ float g_u [NR * RR];      // u[j,r] = fp[j] . W[r,:]
__device__ float g_ub[NR * RR];      // u + b
__device__ __half g_ph[LL * RR];     // P transposed [l][r], fp16

// ---------------------------------------------------------------------------
// Direct tanh via MUFU: t = 2^(x*2*log2(e)); (t-1)/(t+1). ~1e-7 abs err.
// ---------------------------------------------------------------------------
__device__ __forceinline__ float tanh_dir(float x) {
    float t;
    asm("ex2.approx.f32 %0, %1;" : "=f"(t) : "f"(x * 2.8853900817779268f));
    float r;
    asm("rcp.approx.f32 %0, %1;" : "=f"(r) : "f"(t + 1.0f));
    return (t - 1.0f) * r;
}

__device__ __forceinline__ uint32_t smem_u32(const void* p) {
    uint32_t a;
    asm("{ .reg .u64 t; cvta.to.shared.u64 t, %1; cvt.u32.u64 %0, t; }" : "=r"(a) : "l"(p));
    return a;
}

__device__ __forceinline__ void ldsm_x4(uint32_t& r0, uint32_t& r1,
                                        uint32_t& r2, uint32_t& r3, uint32_t addr) {
    asm volatile("ldmatrix.sync.aligned.m8n8.x4.shared.b16 {%0,%1,%2,%3}, [%4];"
        : "=r"(r0), "=r"(r1), "=r"(r2), "=r"(r3) : "r"(addr));
}

__device__ __forceinline__ void mma_fp16(float* d, const uint32_t* a,
                                         uint32_t b0, uint32_t b1) {
    asm volatile(
        "mma.sync.aligned.m16n8k16.row.col.f32.f16.f16.f32 "
        "{%0,%1,%2,%3}, {%4,%5,%6,%7}, {%8,%9}, {%0,%1,%2,%3};\n"
        : "+f"(d[0]), "+f"(d[1]), "+f"(d[2]), "+f"(d[3])
        : "r"(a[0]), "r"(a[1]), "r"(a[2]), "r"(a[3]), "r"(b0), "r"(b1));
}

#define CP_A8(dst, src) \
    asm volatile("cp.async.ca.shared.global [%0], [%1], 8;" :: "r"(dst), "l"(src))
#define CP_A16(dst, src) \
    asm volatile("cp.async.cg.shared.global [%0], [%1], 16;" :: "r"(dst), "l"(src))
#define CP_COMMIT() asm volatile("cp.async.commit_group;" ::: "memory")
#define CP_WAIT1()  asm volatile("cp.async.wait_group 1;" ::: "memory")
#define CP_WAIT0()  asm volatile("cp.async.wait_group 0;" ::: "memory")

// ---------------------------------------------------------------------------
// Kernel A: u = fp @ W^T ; store u and u+b. (P-convert folded in, grid.x==13.)
// ---------------------------------------------------------------------------
#define SAW 36
#define SBW 68

__global__ void __launch_bounds__(128, 4)
compute_u_kernel(const float* __restrict__ x,
                 const float* __restrict__ W,
                 const float* __restrict__ b,
                 const float* __restrict__ P) {
    if (blockIdx.x == 13) {
        int t0 = blockIdx.y * 128 + threadIdx.x;
        for (int idx = t0; idx < LL * RR; idx += 2048) {
            int l = idx >> 10;
            int r = idx & 1023;
            g_ph[idx] = __float2half_rn(P[r * LL + l]);
        }
        return;
    }

    __shared__ float As[32][SAW];
    __shared__ float Bs[32][SBW];

    const int tid = threadIdx.x;
    const int j0 = blockIdx.x * 32;
    const int r0 = blockIdx.y * 64;

    const int am = tid & 31;
    const int akb = (tid >> 5) * 8;
    int jj = j0 + am; if (jj > NR - 1) jj = NR - 1;

    const int bn = tid & 63;
    const int bkh = (tid >> 6) * 16;

    const int m0 = (tid >> 4) * 4;
    const int n0 = (tid & 15) * 4;

    float ar[8], br[16];
    float acc[4][4] = {};

    {
        const float* ap = x + (size_t)jj * DD + akb;
        *(float4*)&ar[0] = *(const float4*)&ap[0];
        *(float4*)&ar[4] = *(const float4*)&ap[4];
        const float* bp = W + (size_t)(r0 + bn) * DD + bkh;
        #pragma unroll
        for (int q = 0; q < 4; q++)
            *(float4*)&br[q * 4] = *(const float4*)&bp[q * 4];
    }

    #pragma unroll 1
    for (int c = 0; c < DD / 32; c++) {
        __syncthreads();
        #pragma unroll
        for (int q = 0; q < 8; q++) As[akb + q][am] = ar[q];
        #pragma unroll
        for (int q = 0; q < 16; q++) Bs[bkh + q][bn] = br[q];
        __syncthreads();

        if (c < DD / 32 - 1) {
            const int kc = (c + 1) * 32;
            const int neg = (kc >= HALF);
            const float* ap = x + (size_t)(jj + neg) * DD + kc + akb;
            *(float4*)&ar[0] = *(const float4*)&ap[0];
            *(float4*)&ar[4] = *(const float4*)&ap[4];
            if (neg) {
                #pragma unroll
                for (int q = 0; q < 8; q++) ar[q] = -ar[q];
            }
            const float* bp = W + (size_t)(r0 + bn) * DD + kc + bkh;
            #pragma unroll
            for (int q = 0; q < 4; q++)
                *(float4*)&br[q * 4] = *(const float4*)&bp[q * 4];
        }

        #pragma unroll 8
        for (int k = 0; k < 32; k++) {
            float4 a4 = *(const float4*)&As[k][m0];
            float4 b4 = *(const float4*)&Bs[k][n0];
            acc[0][0] += a4.x * b4.x; acc[0][1] += a4.x * b4.y;
            acc[0][2] += a4.x * b4.z; acc[0][3] += a4.x * b4.w;
            acc[1][0] += a4.y * b4.x; acc[1][1] += a4.y * b4.y;
            acc[1][2] += a4.y * b4.z; acc[1][3] += a4.y * b4.w;
            acc[2][0] += a4.z * b4.x; acc[2][1] += a4.z * b4.y;
            acc[2][2] += a4.z * b4.z; acc[2][3] += a4.z * b4.w;
            acc[3][0] += a4.w * b4.x; acc[3][1] += a4.w * b4.y;
            acc[3][2] += a4.w * b4.z; acc[3][3] += a4.w * b4.w;
        }
    }

    float bv[4];
    #pragma unroll
    for (int q = 0; q < 4; q++) bv[q] = __ldg(&b[r0 + n0 + q]);

    #pragma unroll
    for (int mi = 0; mi < 4; mi++) {
        int j = j0 + m0 + mi;
        if (j < NR) {
            size_t base = (size_t)j * RR + r0 + n0;
            #pragma unroll
            for (int ni = 0; ni < 4; ni++) {
                float v = acc[mi][ni];
                g_u [base + ni] = v;
                g_ub[base + ni] = v + bv[ni];
            }
        }
    }
}

// ---------------------------------------------------------------------------
// Kernel B: HMMA pair GEMM, fp16 single-product, ldmatrix frags, cp.async
// double-buffered pipeline. Block: 8 i x 16 j = 128 pairs x 112 labels,
// K chunks of 32.
// ---------------------------------------------------------------------------
#define KC 32
#define SA 34   // f32 stride (136B rows -> 8B-aligned cp.async)
#define SH 40   // half stride (80B rows, 16B-aligned, conflict-free ldmatrix)
#define SB 40

#define STA_SZ (16 * SA * 4)            // 2176 B per buffer
#define STB_SZ (8 * SA * 4)             // 1088
#define BH_SZ  (LL * SB * 2)            // 8960
#define AH_SZ  (128 * SH * 2)           // 10240

#define OFF_STA 0
#define OFF_STB (OFF_STA + 2 * STA_SZ)          // 4352
#define OFF_BH  (OFF_STB + 2 * STB_SZ)          // 6528
#define OFF_AH  (OFF_BH + 2 * BH_SZ)            // 24448
#define SMEM_TOTAL (OFF_AH + 2 * AH_SZ)         // 44928

#define NCHUNK (RR / KC)

__global__ void __launch_bounds__(256, 2)
pair_hmma_kernel(const float* __restrict__ ob, float* __restrict__ out) {
    extern __shared__ char smem[];
    const uint32_t sbase = smem_u32(smem);

    const int tid = threadIdx.x;
    const int wid = tid >> 5;
    const int lane = tid & 31;
    const int g  = lane >> 2;
    const int tg = lane & 3;
    const int i0 = blockIdx.x * 8;
    const int j0 = blockIdx.y * 16;

    const int mw = wid & 3;
    const int nw = wid >> 2;
    const int mbase = mw * 32;
    const int nbase = nw * 56;

    const int hp  = tid & 127;
    const int hk0 = (tid >> 7) * 16;
    const int hjj = hp & 15;
    const int hii = hp >> 4;

    // staging maps: u/ub rows (8B per thread)
    const int srow = tid >> 4, sq = tid & 15;
    int sj = j0 + srow; if (sj > NR - 1) sj = NR - 1;
    int si = i0 + srow; if (si > NR - 1) si = NR - 1;
    const uint64_t gub_addr = (uint64_t)__cvta_generic_to_global(
        (void*)(g_ub + (size_t)sj * RR + sq * 2));
    const uint64_t gu_addr = (uint64_t)__cvta_generic_to_global(
        (void*)(g_u + (size_t)si * RR + sq * 2));

    // P staging map: idx = tid + e*256 < 448; rp = idx>>2, sg = idx&3 (16B seg)
    const int pidx0 = tid;
    const int pidx1 = tid + 256;
    const int prp0 = pidx0 >> 2, psg0 = pidx0 & 3;
    const int prp1 = pidx1 >> 2, psg1 = pidx1 & 3;
    const bool pok1 = (pidx1 < 448);
    const uint64_t gph0 = (uint64_t)__cvta_generic_to_global(
        (void*)(g_ph + (size_t)prp0 * RR + psg0 * 8));
    const uint64_t gph1 = (uint64_t)__cvta_generic_to_global(
        (void*)(g_ph + (size_t)prp1 * RR + psg1 * 8));

    // ldmatrix per-lane addressing
    const int lr = lane & 7;
    const int lmi = lane >> 3;
    const uint32_t a_row_off = (uint32_t)(mbase + lr + (lmi & 1) * 8) * SH * 2;
    const uint32_t a_col_off = (uint32_t)((lmi >> 1) * 8) * 2;
    const uint32_t b_row_off = (uint32_t)(nbase + lr) * SB * 2;
    const uint32_t b_col_off = (uint32_t)((lmi & 1) * 8 + (lmi >> 1) * 16) * 2;

    float acc[2][7][4] = {};

    // ---- stage chunk kc into buffer s via cp.async ----
    auto stage = [&](int kc, int s) {
        uint32_t dsta = sbase + OFF_STA + s * STA_SZ + (srow * SA + sq * 2) * 4;
        CP_A8(dsta, gub_addr + (size_t)kc * 4);
        if (tid < 128) {
            uint32_t dstb = sbase + OFF_STB + s * STB_SZ + (srow * SA + sq * 2) * 4;
            CP_A8(dstb, gu_addr + (size_t)kc * 4);
        }
        {
            uint32_t dbh = sbase + OFF_BH + s * BH_SZ + (prp0 * SB + psg0 * 8) * 2;
            CP_A16(dbh, gph0 + (size_t)kc * 2);
        }
        if (pok1) {
            uint32_t dbh = sbase + OFF_BH + s * BH_SZ + (prp1 * SB + psg1 * 8) * 2;
            CP_A16(dbh, gph1 + (size_t)kc * 2);
        }
    };

    stage(0, 0);
    CP_COMMIT();

    #pragma unroll 1
    for (int c = 0; c < NCHUNK; c++) {
        const int s = c & 1;

        __syncthreads();   // all warps done with buffers from iteration c-1
        if (c + 1 < NCHUNK) {
            stage((c + 1) * KC, 1 - s);
            CP_COMMIT();
            CP_WAIT1();    // chunk c resident, chunk c+1 in flight
        } else {
            CP_WAIT0();
        }
        __syncthreads();

        // h-gen: 16 k-values per thread for pair hp -> fp16 into Ah[s]
        {
            const float* ap = (const float*)(smem + OFF_STA + s * STA_SZ)
                            + hjj * SA + hk0;
            const float* bp = (const float*)(smem + OFF_STB + s * STB_SZ)
                            + hii * SA + hk0;
            __half* ah = (__half*)(smem + OFF_AH + s * AH_SZ);
            #pragma unroll
            for (int kk = 0; kk < 16; kk += 2) {
                float2 av = *(const float2*)&ap[kk];
                float2 bv = *(const float2*)&bp[kk];
                float h0 = tanh_dir(av.x - bv.x);
                float h1 = tanh_dir(av.y - bv.y);
                uint32_t hpk;
                asm("cvt.rn.f16x2.f32 %0, %1, %2;" : "=r"(hpk) : "f"(h1), "f"(h0));
                *(uint32_t*)&ah[hp * SH + hk0 + kk] = hpk;
            }
        }
        __syncthreads();

        const uint32_t ah_base = sbase + OFF_AH + s * AH_SZ;
        const uint32_t bh_base = sbase + OFF_BH + s * BH_SZ;

        // A frags: 2 mf x 2 ks
        uint32_t a[2][2][4];
        #pragma unroll
        for (int ks = 0; ks < 2; ks++) {
            #pragma unroll
            for (int mf = 0; mf < 2; mf++) {
                uint32_t addr = ah_base + a_row_off + (uint32_t)(mf * 16) * SH * 2
                              + a_col_off + (uint32_t)(ks * 16) * 2;
                ldsm_x4(a[ks][mf][0], a[ks][mf][1], a[ks][mf][2], a[ks][mf][3], addr);
            }
        }

        // B frags + MMA (single product)
        #pragma unroll
        for (int nf = 0; nf < 7; nf++) {
            uint32_t boff = b_row_off + (uint32_t)(nf * 8) * SB * 2 + b_col_off;
            uint32_t bhr[4];
            ldsm_x4(bhr[0], bhr[1], bhr[2], bhr[3], bh_base + boff);
            #pragma unroll
            for (int ks = 0; ks < 2; ks++) {
                #pragma unroll
                for (int mf = 0; mf < 2; mf++) {
                    mma_fp16(acc[mf][nf], a[ks][mf], bhr[ks * 2], bhr[ks * 2 + 1]);
                }
            }
        }
    }

    // epilogue
    #pragma unroll
    for (int mf = 0; mf < 2; mf++) {
        const int ii = (mbase >> 4) + mf;
        const int i = i0 + ii;
        const bool iok = (i < NR);
        const int jA = j0 + g;
        const int jB = j0 + g + 8;
        const bool jAok = iok && (jA < NR);
        const bool jBok = iok && (jB < NR);
        float* rowA = out + ((size_t)i * NR + jA) * LL;
        float* rowB = out + ((size_t)i * NR + jB) * LL;
        #pragma unroll
        for (int nf = 0; nf < 7; nf++) {
            int l = nbase + nf * 8 + tg * 2;
            float b0 = __ldg(&ob[l]);
            float b1 = __ldg(&ob[l + 1]);
            if (jAok) {
                float2 v = { acc[mf][nf][0] + b0, acc[mf][nf][1] + b1 };
                *(float2*)&rowA[l] = v;
            }
            if (jBok) {
                float2 v = { acc[mf][nf][2] + b0, acc[mf][nf][3] + b1 };
                *(float2*)&rowB[l] = v;
            }
        }
    }
}

// ---------------------------------------------------------------------------
// Launch. Inputs: x(400x1024), W(1024x1024), b(1024), P(1024x112), out_bias(112)
// ---------------------------------------------------------------------------
extern "C" void kernel_launch(void* const* d_in, const int* in_sizes, int n_in,
                              void* d_out, int out_size) {
    const float* x  = (const float*)d_in[0];
    const float* W  = (const float*)d_in[1];
    const float* b  = (const float*)d_in[2];
    const float* P  = (const float*)d_in[3];
    const float* ob = (const float*)d_in[4];
    float* out = (float*)d_out;

    cudaFuncSetAttribute(pair_hmma_kernel,
                         cudaFuncAttributeMaxDynamicSharedMemorySize, SMEM_TOTAL);

    compute_u_kernel<<<dim3(14, 16), 128>>>(x, W, b, P);
    pair_hmma_kernel<<<dim3(50, 25), 256, SMEM_TOTAL>>>(ob, out);
}